// round 14
// baseline (speedup 1.0000x reference)
#include <cuda_runtime.h>
#include <cuda_fp16.h>
#include <cstdint>
#include <math.h>

#define NN_ 64
#define PP_ 1024
#define EE_ 512
#define HH_ 8
#define MBIG (NN_*PP_)

#define SMEM_BYTES 98304   // 3 stages x (A 8192 + B 8192 halfs)

// ---------------- scratch ---------------------------------------------------
__device__ __half g_xa [(size_t)512*65536];   // x packed-A
__device__ __half g_vp [(size_t)EE_*EE_];     // V packed-B (paired)
__device__ __half g_wp [(size_t)EE_*EE_];     // W^T packed-B (paired)
__device__ __half g_wsp[(size_t)512*65536];   // ws packed-B per (n,h) (paired)
__device__ __half g_wc [(size_t)512*65536];   // W-hat slabs per (n,h) (paired)
__device__ __half g_dp [(size_t)8*229376];    // D-hat packed-A panels per h
__device__ __half g_Ph [(size_t)256*8*16384]; // products fp16
__device__ __half g_yp [(size_t)512*65536];   // y packed-A

#define C7 0.70710678118654752f
__constant__ float DW[8][8] = {
 {1,1,1,1,1,1,1,1}, {1,-1,1,-1,1,-1,1,-1},
 {1,C7,0,-C7,-1,-C7,0,C7}, {0,C7,1,C7,0,-C7,-1,-C7},
 {1,0,-1,0,1,0,-1,0}, {0,1,0,-1,0,1,0,-1},
 {1,-C7,0,C7,-1,C7,0,-C7}, {0,C7,-1,C7,0,-C7,1,-C7}};
#define Q 0.17677669529663687f
__constant__ float MC[8][8] = {
 {.125f,.125f,.25f,0,.25f,0,.25f,0},
 {.125f,-.125f,Q,-Q,0,-.25f,-Q,-Q},
 {.125f,.125f,0,-.25f,-.25f,0,0,.25f},
 {.125f,-.125f,-Q,-Q,0,.25f,Q,-Q},
 {.125f,.125f,-.25f,0,.25f,0,-.25f,0},
 {.125f,-.125f,-Q,Q,0,-.25f,Q,Q},
 {.125f,.125f,0,.25f,-.25f,0,0,-.25f},
 {.125f,-.125f,Q,Q,0,.25f,-Q,Q}};
__constant__ int BK16[28] = {0,4,8,12,16,20,24,28,16,20,24,28,
                             32,36,40,44,32,36,40,44,48,52,56,60,48,52,56,60};
__constant__ int DEND[28] = {-1,0,-1,1,-1,-1,-1,2,-1,-1,-1,3,
                             -1,-1,-1,4,-1,-1,-1,5,-1,-1,-1,6,-1,-1,-1,7};
__constant__ int VID[28]  = {0,0,1,1,2,2,3,3,3,3,2,2,4,4,5,5,5,5,4,4,6,6,7,7,7,7,6,6};
__constant__ float SGN[28]= {1,1,1,1,1,1,-1,-1,1,1,1,1,1,1,-1,-1,1,1,1,1,1,1,-1,-1,1,1,1,1};

// ---------------- helpers ---------------------------------------------------
__device__ __forceinline__ uint32_t smem_u32(const void* p){
    uint32_t a;
    asm("{ .reg .u64 t; cvta.to.shared.u64 t, %1; cvt.u32.u64 %0, t; }":"=r"(a):"l"(p));
    return a;
}
__device__ __forceinline__ uint32_t f2h2(float a, float b){
    __half2 h = __floats2half2_rn(a, b);
    return *(uint32_t*)&h;
}
__device__ __forceinline__ float log_cosh_f(float v){
    float ax = fabsf(v);
    return ax + log1pf(expf(-2.0f*ax)) - 0.6931471805599453f;
}
__device__ __forceinline__ void mma_f16(float c[4], uint4 a, uint32_t b0, uint32_t b1)
{
    asm volatile("mma.sync.aligned.m16n8k16.row.col.f32.f16.f16.f32 "
        "{%0,%1,%2,%3}, {%4,%5,%6,%7}, {%8,%9}, {%0,%1,%2,%3};"
        : "+f"(c[0]), "+f"(c[1]), "+f"(c[2]), "+f"(c[3])
        : "r"(a.x), "r"(a.y), "r"(a.z), "r"(a.w), "r"(b0), "r"(b1));
}

// ---------------- shared mainloop (paired-B) --------------------------------
// Packed-B (paired) per k16 per 64-row slab: [np 4][lane 32][8 halfs];
// uint4(np,l) = frag(nb=2np) ++ frag(nb=2np+1).
__device__ __forceinline__ void gemm_loop(
    const __half* __restrict__ Ap,
    const __half* __restrict__ B0, const __half* __restrict__ B1,
    size_t bstride, int kt, __half* __restrict__ sm, float acc[4][4][4])
{
    const int tid = threadIdx.x, wid = tid >> 5, lane = tid & 31;
    const int wrt = (wid >> 2) * 4, wnp = (wid & 3) * 2;

    auto load_tile = [&](int tt, int buf){
        __half* dA = sm + buf*16384;
        __half* dB = dA + 8192;
        const __half* As = Ap + (size_t)tt*8192;
        #pragma unroll
        for (int i = 0; i < 4; i++) {
            int c = tid + i*256;
            uint32_t dst = smem_u32(dA + c*8);
            asm volatile("cp.async.cg.shared.global [%0], [%1], 16;"
                         :: "r"(dst), "l"(As + c*8));
        }
        #pragma unroll
        for (int i = 0; i < 4; i++) {
            int c = tid + i*256;
            int k16s = c >> 8, r = c & 255;
            const __half* src = ((r & 128) ? B1 : B0)
                              + (size_t)(tt*4 + k16s)*bstride + (r & 127)*8;
            uint32_t dst = smem_u32(dB + k16s*2048 + r*8);
            asm volatile("cp.async.cg.shared.global [%0], [%1], 16;"
                         :: "r"(dst), "l"(src));
        }
        asm volatile("cp.async.commit_group;" ::: "memory");
    };

    load_tile(0, 0);
    if (kt > 1) load_tile(1, 1);

    for (int tt = 0; tt < kt; tt++) {
        const int cur = tt % 3;
        if (tt + 1 < kt) asm volatile("cp.async.wait_group 1;" ::: "memory");
        else             asm volatile("cp.async.wait_group 0;" ::: "memory");
        __syncthreads();
        if (tt + 2 < kt) load_tile(tt + 2, (tt + 2) % 3);

        const uint4* fA  = (const uint4*)(sm + cur*16384);
        const uint4* fB4 = (const uint4*)(sm + cur*16384 + 8192);
        #pragma unroll
        for (int ks = 0; ks < 4; ks++) {
            uint4 a[4]; uint4 b4[2];
            #pragma unroll
            for (int tm = 0; tm < 4; tm++) a[tm] = fA[ks*256 + (wrt + tm)*32 + lane];
            #pragma unroll
            for (int j = 0; j < 2; j++)    b4[j] = fB4[ks*256 + (wnp + j)*32 + lane];
            #pragma unroll
            for (int tm = 0; tm < 4; tm++) {
                mma_f16(acc[tm][0], a[tm], b4[0].x, b4[0].y);
                mma_f16(acc[tm][1], a[tm], b4[0].z, b4[0].w);
                mma_f16(acc[tm][2], a[tm], b4[1].x, b4[1].y);
                mma_f16(acc[tm][3], a[tm], b4[1].z, b4[1].w);
            }
        }
    }
}

// ---------------- Stage 1: ws = x @ V^T -> paired packed-B slabs ------------
__global__ __launch_bounds__(256, 2) void k_stage1()
{
    extern __shared__ __half smh[];
    const int bn = blockIdx.x * 128, bm = blockIdx.y * 128;
    float acc[4][4][4] = {};
    const __half* b0 = g_vp + (bn >> 3) * 128;
    gemm_loop(g_xa + (size_t)(bm >> 7)*65536, b0, b0 + 1024, 8192, 8, smh, acc);

    __syncthreads();
    float* Ts = (float*)smh;
    const int tid = threadIdx.x, wid = tid >> 5, lane = tid & 31;
    const int wm = (wid >> 2) * 64, wn = (wid & 3) * 32;
    const int gg = lane >> 2, tq = lane & 3;
    #pragma unroll
    for (int tm = 0; tm < 4; tm++)
        #pragma unroll
        for (int tn = 0; tn < 4; tn++) {
            int m0 = wm + tm*16 + gg, n0 = wn + tn*8 + 2*tq;
            Ts[(n0    )*132 + m0    ] = acc[tm][tn][0];
            Ts[(n0 + 1)*132 + m0    ] = acc[tm][tn][1];
            Ts[(n0    )*132 + m0 + 8] = acc[tm][tn][2];
            Ts[(n0 + 1)*132 + m0 + 8] = acc[tm][tn][3];
        }
    __syncthreads();

    const int n = bm >> 10, pbase = bm & 1023;
    #pragma unroll
    for (int i = 0; i < 16; i++) {
        int u = tid + i*256;
        int k16rel = u >> 9, rest = u & 511;
        int nbg = rest >> 5, l = rest & 31, g = l >> 2, t = l & 3;
        int hrloc = nbg*8 + g, hrAbs = bn + hrloc;
        const float* ts = Ts + hrloc*132 + k16rel*16 + 2*t;
        uint2 v;
        v.x = f2h2(ts[0], ts[1]);
        v.y = f2h2(ts[8], ts[9]);
        int np = (nbg & 7) >> 1, half = nbg & 1;
        size_t dst = (size_t)(n*8 + (hrAbs >> 6))*65536
                   + (size_t)((pbase >> 4) + k16rel)*1024
                   + np*256 + l*8 + half*4;
        *(uint2*)(g_wsp + dst) = v;
    }
}

// ---------------- DFT over jt on ws slabs (layout-preserving) ---------------
__global__ void k_dft()
{
    const int nh = blockIdx.x, tid = threadIdx.x;
    const __half* slab = g_wsp + (size_t)nh*65536;
    __half* out = g_wc + (size_t)nh*65536;
    #pragma unroll
    for (int it = 0; it < 8; it++) {
        int o4 = tid + it*256;
        float w[8][4];
        #pragma unroll
        for (int jt = 0; jt < 8; jt++) {
            uint2 r = *(const uint2*)(slab + jt*8192 + o4*4);
            __half2 h0 = *(__half2*)&r.x, h1 = *(__half2*)&r.y;
            w[jt][0] = __low2float(h0);  w[jt][1] = __high2float(h0);
            w[jt][2] = __low2float(h1);  w[jt][3] = __high2float(h1);
        }
        #pragma unroll
        for (int c = 0; c < 8; c++) {
            float s[4] = {0,0,0,0};
            #pragma unroll
            for (int jt = 0; jt < 8; jt++) {
                float wgt = DW[c][jt];
                s[0] += wgt*w[jt][0]; s[1] += wgt*w[jt][1];
                s[2] += wgt*w[jt][2]; s[3] += wgt*w[jt][3];
            }
            float sg = (c == 3 || c == 5 || c == 7) ? -1.f : 1.f;
            uint2 v;
            v.x = f2h2(sg*s[0], sg*s[1]);
            v.y = f2h2(sg*s[2], sg*s[3]);
            *(uint2*)(out + c*8192 + o4*4) = v;
        }
    }
}

// ---------------- D-hat packed-A panels from alpha --------------------------
__global__ void k_dmat(const float* __restrict__ alpha)
{
    __shared__ float gs[8][1024];
    const int h = blockIdx.x, tg = blockIdx.y, tid = threadIdx.x;
    for (int i = tid; i < 1024; i += 256) {
        float av[8];
        #pragma unroll
        for (int d = 0; d < 8; d++) av[d] = alpha[h*1024 + ((i + 128*d) & 1023)];
        #pragma unroll
        for (int c = 0; c < 8; c++) {
            float s = 0;
            #pragma unroll
            for (int d = 0; d < 8; d++) s += DW[c][d]*av[d];
            gs[c][i] = s;
        }
    }
    __syncthreads();
    #pragma unroll
    for (int tl = 0; tl < 4; tl++) {
        int t = tg*4 + tl;
        const float* v = gs[VID[t]];
        float s = SGN[t];
        int cb = (t & 1) * 64;
        #pragma unroll
        for (int it = 0; it < 4; it++) {
            int pos = tid + it*256;
            int k16r = pos >> 8, rt = (pos >> 5) & 7, l = pos & 31;
            int g = l >> 2, tq = l & 3;
            int i0 = rt*16 + g, j0 = cb + k16r*16 + 2*tq;
            uint4 o;
            o.x = f2h2(s*v[(j0 - i0) & 1023],     s*v[(j0 + 1 - i0) & 1023]);
            o.y = f2h2(s*v[(j0 - i0 - 8) & 1023], s*v[(j0 - i0 - 7) & 1023]);
            o.z = f2h2(s*v[(j0 + 8 - i0) & 1023], s*v[(j0 + 9 - i0) & 1023]);
            o.w = o.x;
            *(uint4*)(g_dp + (size_t)h*229376 + t*8192 + k16r*2048 + rt*256 + l*8) = o;
        }
    }
}

// ---------------- GEMM2: 8 products per (h, n-pair) -------------------------
__global__ __launch_bounds__(256, 2) void k_gemm2()
{
    extern __shared__ __half smh[];
    const int bp = blockIdx.x, h = blockIdx.y;
    const __half* Ap = g_dp + (size_t)h*229376;
    const __half* B0 = g_wc + (size_t)(bp*16 + h)*65536;
    const __half* B1 = g_wc + (size_t)(bp*16 + 8 + h)*65536;
    __half* Pb = g_Ph + (size_t)(bp*8 + h)*8*16384;

    const int tid = threadIdx.x, wid = tid >> 5, lane = tid & 31;
    const int wrt = (wid >> 2) * 4, wnp = (wid & 3) * 2;
    const int wm = (wid >> 2) * 64, wn = (wid & 3) * 32;
    const int gg = lane >> 2, tq = lane & 3;
    float acc[4][4][4] = {};

    auto load_tile = [&](int tt, int buf){
        __half* dA = smh + buf*16384;
        __half* dB = dA + 8192;
        const __half* As = Ap + (size_t)tt*8192;
        #pragma unroll
        for (int i = 0; i < 4; i++) {
            int c = tid + i*256;
            uint32_t dst = smem_u32(dA + c*8);
            asm volatile("cp.async.cg.shared.global [%0], [%1], 16;"
                         :: "r"(dst), "l"(As + c*8));
        }
        int kb = BK16[tt];
        #pragma unroll
        for (int i = 0; i < 4; i++) {
            int c = tid + i*256;
            int k16s = c >> 8, r = c & 255;
            const __half* src = ((r & 128) ? B1 : B0)
                              + (size_t)(kb + k16s)*1024 + (r & 127)*8;
            uint32_t dst = smem_u32(dB + k16s*2048 + r*8);
            asm volatile("cp.async.cg.shared.global [%0], [%1], 16;"
                         :: "r"(dst), "l"(src));
        }
        asm volatile("cp.async.commit_group;" ::: "memory");
    };

    load_tile(0, 0);
    load_tile(1, 1);

    for (int tt = 0; tt < 28; tt++) {
        const int cur = tt % 3;
        if (tt + 1 < 28) asm volatile("cp.async.wait_group 1;" ::: "memory");
        else             asm volatile("cp.async.wait_group 0;" ::: "memory");
        __syncthreads();
        if (tt + 2 < 28) load_tile(tt + 2, (tt + 2) % 3);

        const uint4* fA  = (const uint4*)(smh + cur*16384);
        const uint4* fB4 = (const uint4*)(smh + cur*16384 + 8192);
        #pragma unroll
        for (int ks = 0; ks < 4; ks++) {
            uint4 a[4]; uint4 b4[2];
            #pragma unroll
            for (int tm = 0; tm < 4; tm++) a[tm] = fA[ks*256 + (wrt + tm)*32 + lane];
            #pragma unroll
            for (int j = 0; j < 2; j++)    b4[j] = fB4[ks*256 + (wnp + j)*32 + lane];
            #pragma unroll
            for (int tm = 0; tm < 4; tm++) {
                mma_f16(acc[tm][0], a[tm], b4[0].x, b4[0].y);
                mma_f16(acc[tm][1], a[tm], b4[0].z, b4[0].w);
                mma_f16(acc[tm][2], a[tm], b4[1].x, b4[1].y);
                mma_f16(acc[tm][3], a[tm], b4[1].z, b4[1].w);
            }
        }

        int dc = DEND[tt];
        if (dc >= 0) {
            __half* d = Pb + (size_t)dc*16384;
            #pragma unroll
            for (int tm = 0; tm < 4; tm++)
                #pragma unroll
                for (int tn = 0; tn < 4; tn++) {
                    int m0 = wm + tm*16 + gg, c0 = wn + tn*8 + 2*tq;
                    *(uint32_t*)(d + (m0    )*128 + c0) = f2h2(acc[tm][tn][0], acc[tm][tn][1]);
                    *(uint32_t*)(d + (m0 + 8)*128 + c0) = f2h2(acc[tm][tn][2], acc[tm][tn][3]);
                    acc[tm][tn][0] = acc[tm][tn][1] = acc[tm][tn][2] = acc[tm][tn][3] = 0.f;
                }
        }
    }
}

// ---------------- Combine: y_pt = sum_c MC[pt][c] P_c -> packed-A y ---------
__global__ void k_cmb()
{
    const int bp = blockIdx.x, h = blockIdx.y, tid = threadIdx.x;
    const __half* Pb = g_Ph + (size_t)(bp*8 + h)*8*16384;
    #pragma unroll
    for (int it = 0; it < 8; it++) {
        int task = tid + it*256;
        int nhalf = task >> 10, rest = task & 1023;
        int k16n = rest >> 8, rt = (rest >> 5) & 7, l = rest & 31;
        int g = l >> 2, tq = l & 3;
        int i0 = rt*16 + g;
        int col = nhalf*64 + k16n*16 + 2*tq;

        float y[8][8];
        #pragma unroll
        for (int pt = 0; pt < 8; pt++)
            #pragma unroll
            for (int q = 0; q < 8; q++) y[pt][q] = 0.f;

        #pragma unroll
        for (int c = 0; c < 8; c++) {
            const __half* base = Pb + (size_t)c*16384;
            __half2 a0 = *(const __half2*)(base + (i0    )*128 + col);
            __half2 a1 = *(const __half2*)(base + (i0 + 8)*128 + col);
            __half2 a2 = *(const __half2*)(base + (i0    )*128 + col + 8);
            __half2 a3 = *(const __half2*)(base + (i0 + 8)*128 + col + 8);
            float f0x = __low2float(a0), f0y = __high2float(a0);
            float f1x = __low2float(a1), f1y = __high2float(a1);
            float f2x = __low2float(a2), f2y = __high2float(a2);
            float f3x = __low2float(a3), f3y = __high2float(a3);
            #pragma unroll
            for (int pt = 0; pt < 8; pt++) {
                float m = MC[pt][c];
                y[pt][0] += m*f0x; y[pt][1] += m*f0y;
                y[pt][2] += m*f1x; y[pt][3] += m*f1y;
                y[pt][4] += m*f2x; y[pt][5] += m*f2y;
                y[pt][6] += m*f3x; y[pt][7] += m*f3y;
            }
        }
        #pragma unroll
        for (int pt = 0; pt < 8; pt++) {
            uint4 v;
            v.x = f2h2(y[pt][0], y[pt][1]);
            v.y = f2h2(y[pt][2], y[pt][3]);
            v.z = f2h2(y[pt][4], y[pt][5]);
            v.w = f2h2(y[pt][6], y[pt][7]);
            int panel = (bp*2 + nhalf)*8 + pt;
            *(uint4*)(g_yp + (size_t)panel*65536 + (h*4 + k16n)*2048 + rt*256 + l*8) = v;
        }
    }
}

// ---------------- Stage 3: out = log_cosh(y @ W + b) ------------------------
__global__ __launch_bounds__(256, 2) void k_stage3(const float* __restrict__ bias,
                                                   float* __restrict__ out)
{
    extern __shared__ __half smh[];
    const int bn = blockIdx.x * 128, bm = blockIdx.y * 128;
    float acc[4][4][4] = {};
    const __half* b0 = g_wp + (bn >> 3) * 128;
    gemm_loop(g_yp + (size_t)(bm >> 7)*65536, b0, b0 + 1024, 8192, 8, smh, acc);

    const int tid = threadIdx.x, wid = tid >> 5, lane = tid & 31;
    const int wm = (wid >> 2) * 64, wn = (wid & 3) * 32;
    const int gg = lane >> 2, tq = lane & 3;
    #pragma unroll
    for (int tn = 0; tn < 4; tn++) {
        int n0 = wn + tn*8 + 2*tq;
        float bb0 = bias[bn + n0], bb1 = bias[bn + n0 + 1];
        #pragma unroll
        for (int tm = 0; tm < 4; tm++) {
            int m0 = bm + wm + tm*16 + gg;
            float2 v0 = make_float2(log_cosh_f(acc[tm][tn][0] + bb0),
                                    log_cosh_f(acc[tm][tn][1] + bb1));
            float2 v1 = make_float2(log_cosh_f(acc[tm][tn][2] + bb0),
                                    log_cosh_f(acc[tm][tn][3] + bb1));
            *(float2*)(out + (size_t)(m0    )*EE_ + bn + n0) = v0;
            *(float2*)(out + (size_t)(m0 + 8)*EE_ + bn + n0) = v1;
        }
    }
}

// ---------------- pack kernels ----------------------------------------------
__global__ void k_pack_x(const float* __restrict__ x)
{
    __shared__ float S[128*68];
    const int panel = blockIdx.x, kslab = blockIdx.y;
    const int tid = threadIdx.x;
    #pragma unroll
    for (int i = 0; i < 8; i++) {
        int c = tid + i*256, row = c >> 4, seg = c & 15;
        float4 v = *(const float4*)(x + (size_t)(panel*128 + row)*512 + kslab*64 + seg*4);
        *(float4*)(S + row*68 + seg*4) = v;
    }
    __syncthreads();
    #pragma unroll
    for (int i = 0; i < 4; i++) {
        int u = tid + i*256;
        int k16 = u >> 8, rt = (u >> 5) & 7, l = u & 31;
        int g = l >> 2, t = l & 3;
        const float* s0 = S + (rt*16 + g)*68 + k16*16 + 2*t;
        const float* s1 = s0 + 8*68;
        uint4 v;
        v.x = f2h2(s0[0], s0[1]); v.y = f2h2(s1[0], s1[1]);
        v.z = f2h2(s0[8], s0[9]); v.w = f2h2(s1[8], s1[9]);
        *(uint4*)(g_xa + (size_t)panel*65536 + (size_t)(kslab*4 + k16)*2048
                  + rt*256 + l*8) = v;
    }
}

// paired packed-B producers: uint4(np,l) = frag(nb=2np) ++ frag(nb=2np+1)
__global__ void k_pack_v(const float* __restrict__ V)   // grid (32 k16, 4)
{
    int k16 = blockIdx.x, np = blockIdx.y*8 + (threadIdx.x >> 5), l = threadIdx.x & 31;
    int g = l >> 2, t = l & 3;
    int r0 = np*16 + g, r1 = r0 + 8, k = k16*16 + 2*t;
    uint4 v;
    v.x = f2h2(V[(size_t)r0*512 + k    ], V[(size_t)r0*512 + k + 1]);
    v.y = f2h2(V[(size_t)r0*512 + k + 8], V[(size_t)r0*512 + k + 9]);
    v.z = f2h2(V[(size_t)r1*512 + k    ], V[(size_t)r1*512 + k + 1]);
    v.w = f2h2(V[(size_t)r1*512 + k + 8], V[(size_t)r1*512 + k + 9]);
    *(uint4*)(g_vp + k16*8192 + np*256 + l*8) = v;
}

__global__ void k_pack_w(const float* __restrict__ W)   // grid (32 k16, 4)
{
    int k16 = blockIdx.x, np = blockIdx.y*8 + (threadIdx.x >> 5), l = threadIdx.x & 31;
    int g = l >> 2, t = l & 3;
    int e0 = np*16 + g, e1 = e0 + 8, k = k16*16 + 2*t;
    uint4 v;
    v.x = f2h2(W[(size_t)(k    )*512 + e0], W[(size_t)(k + 1)*512 + e0]);
    v.y = f2h2(W[(size_t)(k + 8)*512 + e0], W[(size_t)(k + 9)*512 + e0]);
    v.z = f2h2(W[(size_t)(k    )*512 + e1], W[(size_t)(k + 1)*512 + e1]);
    v.w = f2h2(W[(size_t)(k + 8)*512 + e1], W[(size_t)(k + 9)*512 + e1]);
    *(uint4*)(g_wp + k16*8192 + np*256 + l*8) = v;
}

// ---------------------------------------------------------------------------
extern "C" void kernel_launch(void* const* d_in, const int* in_sizes, int n_in,
                              void* d_out, int out_size)
{
    const float* x     = (const float*)d_in[0];
    const float* alpha = (const float*)d_in[1];
    const float* V     = (const float*)d_in[2];
    const float* W     = (const float*)d_in[3];
    const float* b     = (const float*)d_in[4];
    float* out = (float*)d_out;

    cudaFuncSetAttribute(k_stage1, cudaFuncAttributeMaxDynamicSharedMemorySize, SMEM_BYTES);
    cudaFuncSetAttribute(k_gemm2, cudaFuncAttributeMaxDynamicSharedMemorySize, SMEM_BYTES);
    cudaFuncSetAttribute(k_stage3, cudaFuncAttributeMaxDynamicSharedMemorySize, SMEM_BYTES);

    k_pack_x<<<dim3(512, 8), 256>>>(x);
    k_pack_v<<<dim3(32, 4),  256>>>(V);
    k_pack_w<<<dim3(32, 4),  256>>>(W);
    k_dmat  <<<dim3(8, 7), 256>>>(alpha);

    k_stage1<<<dim3(4, 512), 256, SMEM_BYTES>>>();
    k_dft   <<<512, 256>>>();
    k_gemm2 <<<dim3(32, 8), 256, SMEM_BYTES>>>();
    k_cmb   <<<dim3(32, 8), 256>>>();
    k_stage3<<<dim3(4, 512), 256, SMEM_BYTES>>>(b, out);
}

// round 15
// speedup vs baseline: 1.0291x; 1.0291x over previous
#include <cuda_runtime.h>
#include <cuda_fp16.h>
#include <cstdint>
#include <math.h>

#define NN_ 64
#define PP_ 1024
#define EE_ 512
#define HH_ 8
#define MBIG (NN_*PP_)

#define SMEM_BYTES  98304   // stages 3/gemm2: 3 x (A 8192 + B 8192 halfs)
#define SMEM1_BYTES 86016   // stage1: 3 x (A fp32 128x40 + B 4096 halfs)

// ---------------- scratch ---------------------------------------------------
__device__ __half g_vp [(size_t)EE_*EE_];     // V packed-B
__device__ __half g_wp [(size_t)EE_*EE_];     // W^T packed-B
__device__ __half g_wsp[(size_t)512*65536];   // ws packed-B per (n,h)
__device__ __half g_wc [(size_t)512*65536];   // W-hat slabs per (n,h)
__device__ __half g_dp [(size_t)8*229376];    // D-hat packed-A panels per h
__device__ __half g_Ph [(size_t)256*8*16384]; // products fp16
__device__ __half g_yp [(size_t)512*65536];   // y packed-A

#define C7 0.70710678118654752f
__constant__ float DW[8][8] = {
 {1,1,1,1,1,1,1,1}, {1,-1,1,-1,1,-1,1,-1},
 {1,C7,0,-C7,-1,-C7,0,C7}, {0,C7,1,C7,0,-C7,-1,-C7},
 {1,0,-1,0,1,0,-1,0}, {0,1,0,-1,0,1,0,-1},
 {1,-C7,0,C7,-1,C7,0,-C7}, {0,C7,-1,C7,0,-C7,1,-C7}};
#define Q 0.17677669529663687f
__constant__ float MC[8][8] = {
 {.125f,.125f,.25f,0,.25f,0,.25f,0},
 {.125f,-.125f,Q,-Q,0,-.25f,-Q,-Q},
 {.125f,.125f,0,-.25f,-.25f,0,0,.25f},
 {.125f,-.125f,-Q,-Q,0,.25f,Q,-Q},
 {.125f,.125f,-.25f,0,.25f,0,-.25f,0},
 {.125f,-.125f,-Q,Q,0,-.25f,Q,Q},
 {.125f,.125f,0,.25f,-.25f,0,0,-.25f},
 {.125f,-.125f,Q,Q,0,.25f,-Q,Q}};
__constant__ int BK16[28] = {0,4,8,12,16,20,24,28,16,20,24,28,
                             32,36,40,44,32,36,40,44,48,52,56,60,48,52,56,60};
__constant__ int DEND[28] = {-1,0,-1,1,-1,-1,-1,2,-1,-1,-1,3,
                             -1,-1,-1,4,-1,-1,-1,5,-1,-1,-1,6,-1,-1,-1,7};
__constant__ int VID[28]  = {0,0,1,1,2,2,3,3,3,3,2,2,4,4,5,5,5,5,4,4,6,6,7,7,7,7,6,6};
__constant__ float SGN[28]= {1,1,1,1,1,1,-1,-1,1,1,1,1,1,1,-1,-1,1,1,1,1,1,1,-1,-1,1,1,1,1};

// ---------------- helpers ---------------------------------------------------
__device__ __forceinline__ uint32_t smem_u32(const void* p){
    uint32_t a;
    asm("{ .reg .u64 t; cvta.to.shared.u64 t, %1; cvt.u32.u64 %0, t; }":"=r"(a):"l"(p));
    return a;
}
__device__ __forceinline__ uint32_t f2h2(float a, float b){
    __half2 h = __floats2half2_rn(a, b);
    return *(uint32_t*)&h;
}
__device__ __forceinline__ float log_cosh_f(float v){
    float ax = fabsf(v);
    return ax + log1pf(expf(-2.0f*ax)) - 0.6931471805599453f;
}
__device__ __forceinline__ void mma_f16(float c[4], uint4 a, uint2 b)
{
    asm volatile("mma.sync.aligned.m16n8k16.row.col.f32.f16.f16.f32 "
        "{%0,%1,%2,%3}, {%4,%5,%6,%7}, {%8,%9}, {%0,%1,%2,%3};"
        : "+f"(c[0]), "+f"(c[1]), "+f"(c[2]), "+f"(c[3])
        : "r"(a.x), "r"(a.y), "r"(a.z), "r"(a.w), "r"(b.x), "r"(b.y));
}

// ---------------- shared mainloop (packed A+B; stages 3 / gemm2) ------------
__device__ __forceinline__ void gemm_loop(
    const __half* __restrict__ Ap,
    const __half* __restrict__ B0, const __half* __restrict__ B1,
    size_t bstride, int kt, __half* __restrict__ sm, float acc[4][4][4])
{
    const int tid = threadIdx.x, wid = tid >> 5, lane = tid & 31;
    const int wrt = (wid >> 2) * 4, wnb = (wid & 3) * 4;

    auto load_tile = [&](int tt, int buf){
        __half* dA = sm + buf*16384;
        __half* dB = dA + 8192;
        const __half* As = Ap + (size_t)tt*8192;
        #pragma unroll
        for (int i = 0; i < 4; i++) {
            int c = tid + i*256;
            uint32_t dst = smem_u32(dA + c*8);
            asm volatile("cp.async.cg.shared.global [%0], [%1], 16;"
                         :: "r"(dst), "l"(As + c*8));
        }
        #pragma unroll
        for (int i = 0; i < 4; i++) {
            int c = tid + i*256;
            int k16s = c >> 8, r = c & 255, nb = r >> 4, lp = r & 15;
            const __half* src = ((nb & 8) ? B1 : B0)
                              + (size_t)(tt*4 + k16s)*bstride + (nb & 7)*128 + lp*8;
            uint32_t dst = smem_u32(dB + k16s*2048 + nb*128 + lp*8);
            asm volatile("cp.async.cg.shared.global [%0], [%1], 16;"
                         :: "r"(dst), "l"(src));
        }
        asm volatile("cp.async.commit_group;" ::: "memory");
    };

    load_tile(0, 0);
    if (kt > 1) load_tile(1, 1);

    for (int tt = 0; tt < kt; tt++) {
        const int cur = tt % 3;
        if (tt + 1 < kt) asm volatile("cp.async.wait_group 1;" ::: "memory");
        else             asm volatile("cp.async.wait_group 0;" ::: "memory");
        __syncthreads();
        if (tt + 2 < kt) load_tile(tt + 2, (tt + 2) % 3);

        const uint4* fA = (const uint4*)(sm + cur*16384);
        const uint2* fB = (const uint2*)(sm + cur*16384 + 8192);
        #pragma unroll
        for (int ks = 0; ks < 4; ks++) {
            uint4 a[4]; uint2 b[4];
            #pragma unroll
            for (int tm = 0; tm < 4; tm++) a[tm] = fA[ks*256 + (wrt + tm)*32 + lane];
            #pragma unroll
            for (int tn = 0; tn < 4; tn++) b[tn] = fB[ks*512 + (wnb + tn)*32 + lane];
            #pragma unroll
            for (int tm = 0; tm < 4; tm++)
                #pragma unroll
                for (int tn = 0; tn < 4; tn++)
                    mma_f16(acc[tm][tn], a[tm], b[tn]);
        }
    }
}

// ---------------- Stage 1: ws = x @ V^T (raw fp32 A, fused rounding) --------
// A tiles BK=32 fp32 in smem, stride 40 floats (conflict-free). 3-stage pipe.
__global__ __launch_bounds__(256, 2) void k_stage1(const float* __restrict__ x)
{
    extern __shared__ __half smh[];
    char* smc = (char*)smh;
    const int bn = blockIdx.x * 128, bm = blockIdx.y * 128;
    const __half* B0 = g_vp + (bn >> 3) * 128;
    const __half* B1 = B0 + 1024;
    const float* Ax = x + (size_t)bm*512;

    const int tid = threadIdx.x, wid = tid >> 5, lane = tid & 31;
    const int wrt = (wid >> 2) * 4, wnb = (wid & 3) * 4;
    const int gg = lane >> 2, tq = lane & 3;
    float acc[4][4][4] = {};

    // per stage: A fp32 128x40 = 20480 B, B 4096 halfs = 8192 B -> 28672 B
    auto load_tile = [&](int tt, int buf){
        float* dA = (float*)(smc + buf*28672);
        __half* dB = (__half*)(smc + buf*28672 + 20480);
        #pragma unroll
        for (int i = 0; i < 4; i++) {                 // A: 1024 x 16B chunks
            int c = tid + i*256;
            int row = c >> 3, seg = c & 7;
            uint32_t dst = smem_u32(dA + row*40 + seg*4);
            asm volatile("cp.async.cg.shared.global [%0], [%1], 16;"
                         :: "r"(dst), "l"(Ax + (size_t)row*512 + tt*32 + seg*4));
        }
        #pragma unroll
        for (int i = 0; i < 2; i++) {                 // B: 512 x 16B chunks
            int c = tid + i*256;
            int k16s = c >> 8, r = c & 255, nb = r >> 4, lp = r & 15;
            const __half* src = ((nb & 8) ? B1 : B0)
                              + (size_t)(tt*2 + k16s)*8192 + (nb & 7)*128 + lp*8;
            uint32_t dst = smem_u32(dB + k16s*2048 + nb*128 + lp*8);
            asm volatile("cp.async.cg.shared.global [%0], [%1], 16;"
                         :: "r"(dst), "l"(src));
        }
        asm volatile("cp.async.commit_group;" ::: "memory");
    };

    load_tile(0, 0);
    load_tile(1, 1);

    for (int tt = 0; tt < 16; tt++) {
        const int cur = tt % 3;
        if (tt + 1 < 16) asm volatile("cp.async.wait_group 1;" ::: "memory");
        else             asm volatile("cp.async.wait_group 0;" ::: "memory");
        __syncthreads();
        if (tt + 2 < 16) load_tile(tt + 2, (tt + 2) % 3);

        const float* cA = (const float*)(smc + cur*28672);
        const uint2* fB = (const uint2*)(smc + cur*28672 + 20480);
        #pragma unroll
        for (int ks = 0; ks < 2; ks++) {
            const int k0 = ks*16 + 2*tq;
            uint4 a[4]; uint2 b[4];
            #pragma unroll
            for (int tm = 0; tm < 4; tm++) {
                int r0 = (wrt + tm)*16 + gg;
                float2 p0 = *(const float2*)(cA + r0*40 + k0);
                float2 p1 = *(const float2*)(cA + (r0+8)*40 + k0);
                float2 p2 = *(const float2*)(cA + r0*40 + k0 + 8);
                float2 p3 = *(const float2*)(cA + (r0+8)*40 + k0 + 8);
                a[tm].x = f2h2(p0.x, p0.y);
                a[tm].y = f2h2(p1.x, p1.y);
                a[tm].z = f2h2(p2.x, p2.y);
                a[tm].w = f2h2(p3.x, p3.y);
            }
            #pragma unroll
            for (int tn = 0; tn < 4; tn++) b[tn] = fB[ks*512 + (wnb + tn)*32 + lane];
            #pragma unroll
            for (int tm = 0; tm < 4; tm++)
                #pragma unroll
                for (int tn = 0; tn < 4; tn++)
                    mma_f16(acc[tm][tn], a[tm], b[tn]);
        }
    }

    __syncthreads();
    float* Ts = (float*)smh;   // 128*132*4 = 67584 B <= 86016
    const int wm = (wid >> 2) * 64, wn = (wid & 3) * 32;
    #pragma unroll
    for (int tm = 0; tm < 4; tm++)
        #pragma unroll
        for (int tn = 0; tn < 4; tn++) {
            int m0 = wm + tm*16 + gg, n0 = wn + tn*8 + 2*tq;
            Ts[(n0    )*132 + m0    ] = acc[tm][tn][0];
            Ts[(n0 + 1)*132 + m0    ] = acc[tm][tn][1];
            Ts[(n0    )*132 + m0 + 8] = acc[tm][tn][2];
            Ts[(n0 + 1)*132 + m0 + 8] = acc[tm][tn][3];
        }
    __syncthreads();

    const int n = bm >> 10, pbase = bm & 1023;
    #pragma unroll
    for (int i = 0; i < 16; i++) {
        int u = tid + i*256;
        int k16rel = u >> 9, rest = u & 511;
        int nbg = rest >> 5, l = rest & 31, g = l >> 2, t = l & 3;
        int hrloc = nbg*8 + g, hrAbs = bn + hrloc;
        const float* ts = Ts + hrloc*132 + k16rel*16 + 2*t;
        uint2 v;
        v.x = f2h2(ts[0], ts[1]);
        v.y = f2h2(ts[8], ts[9]);
        size_t dst = (size_t)(n*8 + (hrAbs >> 6))*65536
                   + (size_t)((pbase >> 4) + k16rel)*1024
                   + ((hrAbs >> 3) & 7)*128 + l*4;
        *(uint2*)(g_wsp + dst) = v;
    }
}

// ---------------- DFT over jt on ws slabs (layout-preserving) ---------------
__global__ void k_dft()
{
    const int nh = blockIdx.x, tid = threadIdx.x;
    const __half* slab = g_wsp + (size_t)nh*65536;
    __half* out = g_wc + (size_t)nh*65536;
    #pragma unroll
    for (int it = 0; it < 8; it++) {
        int o4 = tid + it*256;
        float w[8][4];
        #pragma unroll
        for (int jt = 0; jt < 8; jt++) {
            uint2 r = *(const uint2*)(slab + jt*8192 + o4*4);
            __half2 h0 = *(__half2*)&r.x, h1 = *(__half2*)&r.y;
            w[jt][0] = __low2float(h0);  w[jt][1] = __high2float(h0);
            w[jt][2] = __low2float(h1);  w[jt][3] = __high2float(h1);
        }
        #pragma unroll
        for (int c = 0; c < 8; c++) {
            float s[4] = {0,0,0,0};
            #pragma unroll
            for (int jt = 0; jt < 8; jt++) {
                float wgt = DW[c][jt];
                s[0] += wgt*w[jt][0]; s[1] += wgt*w[jt][1];
                s[2] += wgt*w[jt][2]; s[3] += wgt*w[jt][3];
            }
            float sg = (c == 3 || c == 5 || c == 7) ? -1.f : 1.f;
            uint2 v;
            v.x = f2h2(sg*s[0], sg*s[1]);
            v.y = f2h2(sg*s[2], sg*s[3]);
            *(uint2*)(out + c*8192 + o4*4) = v;
        }
    }
}

// ---------------- D-hat packed-A panels from alpha --------------------------
__global__ void k_dmat(const float* __restrict__ alpha)
{
    __shared__ float gs[8][1024];
    const int h = blockIdx.x, tg = blockIdx.y, tid = threadIdx.x;
    for (int i = tid; i < 1024; i += 256) {
        float av[8];
        #pragma unroll
        for (int d = 0; d < 8; d++) av[d] = alpha[h*1024 + ((i + 128*d) & 1023)];
        #pragma unroll
        for (int c = 0; c < 8; c++) {
            float s = 0;
            #pragma unroll
            for (int d = 0; d < 8; d++) s += DW[c][d]*av[d];
            gs[c][i] = s;
        }
    }
    __syncthreads();
    #pragma unroll
    for (int tl = 0; tl < 4; tl++) {
        int t = tg*4 + tl;
        const float* v = gs[VID[t]];
        float s = SGN[t];
        int cb = (t & 1) * 64;
        #pragma unroll
        for (int it = 0; it < 4; it++) {
            int pos = tid + it*256;
            int k16r = pos >> 8, rt = (pos >> 5) & 7, l = pos & 31;
            int g = l >> 2, tq = l & 3;
            int i0 = rt*16 + g, j0 = cb + k16r*16 + 2*tq;
            uint4 o;
            o.x = f2h2(s*v[(j0 - i0) & 1023],     s*v[(j0 + 1 - i0) & 1023]);
            o.y = f2h2(s*v[(j0 - i0 - 8) & 1023], s*v[(j0 - i0 - 7) & 1023]);
            o.z = f2h2(s*v[(j0 + 8 - i0) & 1023], s*v[(j0 + 9 - i0) & 1023]);
            o.w = o.x;
            *(uint4*)(g_dp + (size_t)h*229376 + t*8192 + k16r*2048 + rt*256 + l*8) = o;
        }
    }
}

// ---------------- GEMM2: 8 products per (h, n-pair) -------------------------
__global__ __launch_bounds__(256, 2) void k_gemm2()
{
    extern __shared__ __half smh[];
    const int bp = blockIdx.x, h = blockIdx.y;
    const __half* Ap = g_dp + (size_t)h*229376;
    const __half* B0 = g_wc + (size_t)(bp*16 + h)*65536;
    const __half* B1 = g_wc + (size_t)(bp*16 + 8 + h)*65536;
    __half* Pb = g_Ph + (size_t)(bp*8 + h)*8*16384;

    const int tid = threadIdx.x, wid = tid >> 5, lane = tid & 31;
    const int wrt = (wid >> 2) * 4, wnb = (wid & 3) * 4;
    const int wm = (wid >> 2) * 64, wn = (wid & 3) * 32;
    const int gg = lane >> 2, tq = lane & 3;
    float acc[4][4][4] = {};

    auto load_tile = [&](int tt, int buf){
        __half* dA = smh + buf*16384;
        __half* dB = dA + 8192;
        const __half* As = Ap + (size_t)tt*8192;
        #pragma unroll
        for (int i = 0; i < 4; i++) {
            int c = tid + i*256;
            uint32_t dst = smem_u32(dA + c*8);
            asm volatile("cp.async.cg.shared.global [%0], [%1], 16;"
                         :: "r"(dst), "l"(As + c*8));
        }
        int kb = BK16[tt];
        #pragma unroll
        for (int i = 0; i < 4; i++) {
            int c = tid + i*256;
            int k16s = c >> 8, r = c & 255, nb = r >> 4, lp = r & 15;
            const __half* src = ((nb & 8) ? B1 : B0)
                              + (size_t)(kb + k16s)*1024 + (nb & 7)*128 + lp*8;
            uint32_t dst = smem_u32(dB + k16s*2048 + nb*128 + lp*8);
            asm volatile("cp.async.cg.shared.global [%0], [%1], 16;"
                         :: "r"(dst), "l"(src));
        }
        asm volatile("cp.async.commit_group;" ::: "memory");
    };

    load_tile(0, 0);
    load_tile(1, 1);

    for (int tt = 0; tt < 28; tt++) {
        const int cur = tt % 3;
        if (tt + 1 < 28) asm volatile("cp.async.wait_group 1;" ::: "memory");
        else             asm volatile("cp.async.wait_group 0;" ::: "memory");
        __syncthreads();
        if (tt + 2 < 28) load_tile(tt + 2, (tt + 2) % 3);

        const uint4* fA = (const uint4*)(smh + cur*16384);
        const uint2* fB = (const uint2*)(smh + cur*16384 + 8192);
        #pragma unroll
        for (int ks = 0; ks < 4; ks++) {
            uint4 a[4]; uint2 b[4];
            #pragma unroll
            for (int tm = 0; tm < 4; tm++) a[tm] = fA[ks*256 + (wrt + tm)*32 + lane];
            #pragma unroll
            for (int tn = 0; tn < 4; tn++) b[tn] = fB[ks*512 + (wnb + tn)*32 + lane];
            #pragma unroll
            for (int tm = 0; tm < 4; tm++)
                #pragma unroll
                for (int tn = 0; tn < 4; tn++)
                    mma_f16(acc[tm][tn], a[tm], b[tn]);
        }

        int dc = DEND[tt];
        if (dc >= 0) {
            __half* d = Pb + (size_t)dc*16384;
            #pragma unroll
            for (int tm = 0; tm < 4; tm++)
                #pragma unroll
                for (int tn = 0; tn < 4; tn++) {
                    int m0 = wm + tm*16 + gg, c0 = wn + tn*8 + 2*tq;
                    *(uint32_t*)(d + (m0    )*128 + c0) = f2h2(acc[tm][tn][0], acc[tm][tn][1]);
                    *(uint32_t*)(d + (m0 + 8)*128 + c0) = f2h2(acc[tm][tn][2], acc[tm][tn][3]);
                    acc[tm][tn][0] = acc[tm][tn][1] = acc[tm][tn][2] = acc[tm][tn][3] = 0.f;
                }
        }
    }
}

// ---------------- Combine: y_pt = sum_c MC[pt][c] P_c -> packed-A y ---------
__global__ void k_cmb()
{
    const int bp = blockIdx.x, h = blockIdx.y, tid = threadIdx.x;
    const __half* Pb = g_Ph + (size_t)(bp*8 + h)*8*16384;
    #pragma unroll
    for (int it = 0; it < 8; it++) {
        int task = tid + it*256;
        int nhalf = task >> 10, rest = task & 1023;
        int k16n = rest >> 8, rt = (rest >> 5) & 7, l = rest & 31;
        int g = l >> 2, tq = l & 3;
        int i0 = rt*16 + g;
        int col = nhalf*64 + k16n*16 + 2*tq;

        float y[8][8];
        #pragma unroll
        for (int pt = 0; pt < 8; pt++)
            #pragma unroll
            for (int q = 0; q < 8; q++) y[pt][q] = 0.f;

        #pragma unroll
        for (int c = 0; c < 8; c++) {
            const __half* base = Pb + (size_t)c*16384;
            __half2 a0 = *(const __half2*)(base + (i0    )*128 + col);
            __half2 a1 = *(const __half2*)(base + (i0 + 8)*128 + col);
            __half2 a2 = *(const __half2*)(base + (i0    )*128 + col + 8);
            __half2 a3 = *(const __half2*)(base + (i0 + 8)*128 + col + 8);
            float f0x = __low2float(a0), f0y = __high2float(a0);
            float f1x = __low2float(a1), f1y = __high2float(a1);
            float f2x = __low2float(a2), f2y = __high2float(a2);
            float f3x = __low2float(a3), f3y = __high2float(a3);
            #pragma unroll
            for (int pt = 0; pt < 8; pt++) {
                float m = MC[pt][c];
                y[pt][0] += m*f0x; y[pt][1] += m*f0y;
                y[pt][2] += m*f1x; y[pt][3] += m*f1y;
                y[pt][4] += m*f2x; y[pt][5] += m*f2y;
                y[pt][6] += m*f3x; y[pt][7] += m*f3y;
            }
        }
        #pragma unroll
        for (int pt = 0; pt < 8; pt++) {
            uint4 v;
            v.x = f2h2(y[pt][0], y[pt][1]);
            v.y = f2h2(y[pt][2], y[pt][3]);
            v.z = f2h2(y[pt][4], y[pt][5]);
            v.w = f2h2(y[pt][6], y[pt][7]);
            int panel = (bp*2 + nhalf)*8 + pt;
            *(uint4*)(g_yp + (size_t)panel*65536 + (h*4 + k16n)*2048 + rt*256 + l*8) = v;
        }
    }
}

// ---------------- Stage 3: out = log_cosh(y @ W + b) ------------------------
__global__ __launch_bounds__(256, 2) void k_stage3(const float* __restrict__ bias,
                                                   float* __restrict__ out)
{
    extern __shared__ __half smh[];
    const int bn = blockIdx.x * 128, bm = blockIdx.y * 128;
    float acc[4][4][4] = {};
    const __half* b0 = g_wp + (bn >> 3) * 128;
    gemm_loop(g_yp + (size_t)(bm >> 7)*65536, b0, b0 + 1024, 8192, 8, smh, acc);

    const int tid = threadIdx.x, wid = tid >> 5, lane = tid & 31;
    const int wm = (wid >> 2) * 64, wn = (wid & 3) * 32;
    const int gg = lane >> 2, tq = lane & 3;
    #pragma unroll
    for (int tn = 0; tn < 4; tn++) {
        int n0 = wn + tn*8 + 2*tq;
        float bb0 = bias[bn + n0], bb1 = bias[bn + n0 + 1];
        #pragma unroll
        for (int tm = 0; tm < 4; tm++) {
            int m0 = bm + wm + tm*16 + gg;
            float2 v0 = make_float2(log_cosh_f(acc[tm][tn][0] + bb0),
                                    log_cosh_f(acc[tm][tn][1] + bb1));
            float2 v1 = make_float2(log_cosh_f(acc[tm][tn][2] + bb0),
                                    log_cosh_f(acc[tm][tn][3] + bb1));
            *(float2*)(out + (size_t)(m0    )*EE_ + bn + n0) = v0;
            *(float2*)(out + (size_t)(m0 + 8)*EE_ + bn + n0) = v1;
        }
    }
}

// ---------------- pack kernels ----------------------------------------------
__global__ void k_pack_v(const float* __restrict__ V)   // grid (32 k16, 8)
{
    int k16 = blockIdx.x, nb = blockIdx.y*8 + (threadIdx.x >> 5), l = threadIdx.x & 31;
    int g = l >> 2, t = l & 3;
    const float* r = V + (size_t)(nb*8 + g)*512 + k16*16 + 2*t;
    uint2 v;
    v.x = f2h2(r[0], r[1]); v.y = f2h2(r[8], r[9]);
    *(uint2*)(g_vp + k16*8192 + nb*128 + l*4) = v;
}

__global__ void k_pack_w(const float* __restrict__ W)   // grid (32 k16, 8)
{
    int k16 = blockIdx.x, nb = blockIdx.y*8 + (threadIdx.x >> 5), l = threadIdx.x & 31;
    int g = l >> 2, t = l & 3;
    int e = nb*8 + g, k = k16*16 + 2*t;
    uint2 v;
    v.x = f2h2(W[(size_t)(k    )*512 + e], W[(size_t)(k + 1)*512 + e]);
    v.y = f2h2(W[(size_t)(k + 8)*512 + e], W[(size_t)(k + 9)*512 + e]);
    *(uint2*)(g_wp + k16*8192 + nb*128 + l*4) = v;
}

// ---------------------------------------------------------------------------
extern "C" void kernel_launch(void* const* d_in, const int* in_sizes, int n_in,
                              void* d_out, int out_size)
{
    const float* x     = (const float*)d_in[0];
    const float* alpha = (const float*)d_in[1];
    const float* V     = (const float*)d_in[2];
    const float* W     = (const float*)d_in[3];
    const float* b     = (const float*)d_in[4];
    float* out = (float*)d_out;

    cudaFuncSetAttribute(k_stage1, cudaFuncAttributeMaxDynamicSharedMemorySize, SMEM1_BYTES);
    cudaFuncSetAttribute(k_gemm2, cudaFuncAttributeMaxDynamicSharedMemorySize, SMEM_BYTES);
    cudaFuncSetAttribute(k_stage3, cudaFuncAttributeMaxDynamicSharedMemorySize, SMEM_BYTES);

    k_pack_v<<<dim3(32, 8), 256>>>(V);
    k_pack_w<<<dim3(32, 8), 256>>>(W);
    k_dmat  <<<dim3(8, 7), 256>>>(alpha);

    k_stage1<<<dim3(4, 512), 256, SMEM1_BYTES>>>(x);
    k_dft   <<<512, 256>>>();
    k_gemm2 <<<dim3(32, 8), 256, SMEM_BYTES>>>();
    k_cmb   <<<dim3(32, 8), 256>>>();
    k_stage3<<<dim3(4, 512), 256, SMEM_BYTES>>>(b, out);
}

// round 16
// speedup vs baseline: 1.0356x; 1.0063x over previous
#include <cuda_runtime.h>
#include <cuda_fp16.h>
#include <cstdint>
#include <math.h>

#define NN_ 64
#define PP_ 1024
#define EE_ 512
#define HH_ 8
#define MBIG (NN_*PP_)

#define SMEM_BYTES  98304   // stages 3/gemm2: 3 x (A 8192 + B 8192 halfs)
#define SMEM1_BYTES 102400  // stage1: 3 x (A fp32 128x40 + B 8192B) + 2 x fp16A 8192B

// ---------------- scratch ---------------------------------------------------
__device__ __half g_vp [(size_t)EE_*EE_];     // V packed-B
__device__ __half g_wp [(size_t)EE_*EE_];     // W^T packed-B
__device__ __half g_wsp[(size_t)512*65536];   // ws packed-B per (n,h)
__device__ __half g_wc [(size_t)512*65536];   // W-hat slabs per (n,h)
__device__ __half g_dp [(size_t)8*229376];    // D-hat packed-A panels per h
__device__ __half g_Ph [(size_t)256*8*16384]; // products fp16
__device__ __half g_yp [(size_t)512*65536];   // y packed-A

#define C7 0.70710678118654752f
__constant__ float DW[8][8] = {
 {1,1,1,1,1,1,1,1}, {1,-1,1,-1,1,-1,1,-1},
 {1,C7,0,-C7,-1,-C7,0,C7}, {0,C7,1,C7,0,-C7,-1,-C7},
 {1,0,-1,0,1,0,-1,0}, {0,1,0,-1,0,1,0,-1},
 {1,-C7,0,C7,-1,C7,0,-C7}, {0,C7,-1,C7,0,-C7,1,-C7}};
#define Q 0.17677669529663687f
__constant__ float MC[8][8] = {
 {.125f,.125f,.25f,0,.25f,0,.25f,0},
 {.125f,-.125f,Q,-Q,0,-.25f,-Q,-Q},
 {.125f,.125f,0,-.25f,-.25f,0,0,.25f},
 {.125f,-.125f,-Q,-Q,0,.25f,Q,-Q},
 {.125f,.125f,-.25f,0,.25f,0,-.25f,0},
 {.125f,-.125f,-Q,Q,0,-.25f,Q,Q},
 {.125f,.125f,0,.25f,-.25f,0,0,-.25f},
 {.125f,-.125f,Q,Q,0,.25f,-Q,Q}};
__constant__ int BK16[28] = {0,4,8,12,16,20,24,28,16,20,24,28,
                             32,36,40,44,32,36,40,44,48,52,56,60,48,52,56,60};
__constant__ int DEND[28] = {-1,0,-1,1,-1,-1,-1,2,-1,-1,-1,3,
                             -1,-1,-1,4,-1,-1,-1,5,-1,-1,-1,6,-1,-1,-1,7};
__constant__ int VID[28]  = {0,0,1,1,2,2,3,3,3,3,2,2,4,4,5,5,5,5,4,4,6,6,7,7,7,7,6,6};
__constant__ float SGN[28]= {1,1,1,1,1,1,-1,-1,1,1,1,1,1,1,-1,-1,1,1,1,1,1,1,-1,-1,1,1,1,1};

// ---------------- helpers ---------------------------------------------------
__device__ __forceinline__ uint32_t smem_u32(const void* p){
    uint32_t a;
    asm("{ .reg .u64 t; cvta.to.shared.u64 t, %1; cvt.u32.u64 %0, t; }":"=r"(a):"l"(p));
    return a;
}
__device__ __forceinline__ uint32_t f2h2(float a, float b){
    __half2 h = __floats2half2_rn(a, b);
    return *(uint32_t*)&h;
}
__device__ __forceinline__ float log_cosh_f(float v){
    float ax = fabsf(v);
    return ax + log1pf(expf(-2.0f*ax)) - 0.6931471805599453f;
}
__device__ __forceinline__ void mma_f16(float c[4], uint4 a, uint2 b)
{
    asm volatile("mma.sync.aligned.m16n8k16.row.col.f32.f16.f16.f32 "
        "{%0,%1,%2,%3}, {%4,%5,%6,%7}, {%8,%9}, {%0,%1,%2,%3};"
        : "+f"(c[0]), "+f"(c[1]), "+f"(c[2]), "+f"(c[3])
        : "r"(a.x), "r"(a.y), "r"(a.z), "r"(a.w), "r"(b.x), "r"(b.y));
}

// ---------------- shared mainloop (packed A+B; stages 3 / gemm2) ------------
__device__ __forceinline__ void gemm_loop(
    const __half* __restrict__ Ap,
    const __half* __restrict__ B0, const __half* __restrict__ B1,
    size_t bstride, int kt, __half* __restrict__ sm, float acc[4][4][4])
{
    const int tid = threadIdx.x, wid = tid >> 5, lane = tid & 31;
    const int wrt = (wid >> 2) * 4, wnb = (wid & 3) * 4;

    auto load_tile = [&](int tt, int buf){
        __half* dA = sm + buf*16384;
        __half* dB = dA + 8192;
        const __half* As = Ap + (size_t)tt*8192;
        #pragma unroll
        for (int i = 0; i < 4; i++) {
            int c = tid + i*256;
            uint32_t dst = smem_u32(dA + c*8);
            asm volatile("cp.async.cg.shared.global [%0], [%1], 16;"
                         :: "r"(dst), "l"(As + c*8));
        }
        #pragma unroll
        for (int i = 0; i < 4; i++) {
            int c = tid + i*256;
            int k16s = c >> 8, r = c & 255, nb = r >> 4, lp = r & 15;
            const __half* src = ((nb & 8) ? B1 : B0)
                              + (size_t)(tt*4 + k16s)*bstride + (nb & 7)*128 + lp*8;
            uint32_t dst = smem_u32(dB + k16s*2048 + nb*128 + lp*8);
            asm volatile("cp.async.cg.shared.global [%0], [%1], 16;"
                         :: "r"(dst), "l"(src));
        }
        asm volatile("cp.async.commit_group;" ::: "memory");
    };

    load_tile(0, 0);
    if (kt > 1) load_tile(1, 1);

    for (int tt = 0; tt < kt; tt++) {
        const int cur = tt % 3;
        if (tt + 1 < kt) asm volatile("cp.async.wait_group 1;" ::: "memory");
        else             asm volatile("cp.async.wait_group 0;" ::: "memory");
        __syncthreads();
        if (tt + 2 < kt) load_tile(tt + 2, (tt + 2) % 3);

        const uint4* fA = (const uint4*)(sm + cur*16384);
        const uint2* fB = (const uint2*)(sm + cur*16384 + 8192);
        #pragma unroll
        for (int ks = 0; ks < 4; ks++) {
            uint4 a[4]; uint2 b[4];
            #pragma unroll
            for (int tm = 0; tm < 4; tm++) a[tm] = fA[ks*256 + (wrt + tm)*32 + lane];
            #pragma unroll
            for (int tn = 0; tn < 4; tn++) b[tn] = fB[ks*512 + (wnb + tn)*32 + lane];
            #pragma unroll
            for (int tm = 0; tm < 4; tm++)
                #pragma unroll
                for (int tn = 0; tn < 4; tn++)
                    mma_f16(acc[tm][tn], a[tm], b[tn]);
        }
    }
}

// ---------------- Stage 1: ws = x @ V^T (fp32 A, cooperative convert) -------
// Per tile (BK=32): cp.async fp32 A (stride 40) + fp16 B; block-wide convert
// writes packed-fp16 A once into a double buffer; mainloop = packed path.
__global__ __launch_bounds__(256, 2) void k_stage1(const float* __restrict__ x)
{
    extern __shared__ __half smh[];
    char* smc = (char*)smh;
    const int bn = blockIdx.x * 128, bm = blockIdx.y * 128;
    const __half* B0 = g_vp + (bn >> 3) * 128;
    const __half* B1 = B0 + 1024;
    const float* Ax = x + (size_t)bm*512;

    const int tid = threadIdx.x, wid = tid >> 5, lane = tid & 31;
    const int wrt = (wid >> 2) * 4, wnb = (wid & 3) * 4;
    const int gg = lane >> 2, tq = lane & 3;
    float acc[4][4][4] = {};

    // per stage: A fp32 128x40 = 20480 B + B 4096 halfs = 8192 B -> 28672 B
    // fp16 A double buffer at 86016: 2 x 8192 B
    auto load_tile = [&](int tt, int buf){
        float* dA = (float*)(smc + buf*28672);
        __half* dB = (__half*)(smc + buf*28672 + 20480);
        #pragma unroll
        for (int i = 0; i < 4; i++) {                 // A: 1024 x 16B chunks
            int c = tid + i*256;
            int row = c >> 3, seg = c & 7;
            uint32_t dst = smem_u32(dA + row*40 + seg*4);
            asm volatile("cp.async.cg.shared.global [%0], [%1], 16;"
                         :: "r"(dst), "l"(Ax + (size_t)row*512 + tt*32 + seg*4));
        }
        #pragma unroll
        for (int i = 0; i < 2; i++) {                 // B: 512 x 16B chunks
            int c = tid + i*256;
            int k16s = c >> 8, r = c & 255, nb = r >> 4, lp = r & 15;
            const __half* src = ((nb & 8) ? B1 : B0)
                              + (size_t)(tt*2 + k16s)*8192 + (nb & 7)*128 + lp*8;
            uint32_t dst = smem_u32(dB + k16s*2048 + nb*128 + lp*8);
            asm volatile("cp.async.cg.shared.global [%0], [%1], 16;"
                         :: "r"(dst), "l"(src));
        }
        asm volatile("cp.async.commit_group;" ::: "memory");
    };

    load_tile(0, 0);
    load_tile(1, 1);

    for (int tt = 0; tt < 16; tt++) {
        const int cur = tt % 3;
        if (tt + 1 < 16) asm volatile("cp.async.wait_group 1;" ::: "memory");
        else             asm volatile("cp.async.wait_group 0;" ::: "memory");
        __syncthreads();                 // fp32 A + B ready; prev fp16 buf free
        if (tt + 2 < 16) load_tile(tt + 2, (tt + 2) % 3);

        // cooperative convert: fp32 tile -> packed fp16 buffer (once)
        const float* cA = (const float*)(smc + cur*28672);
        __half* hA = (__half*)(smc + 86016 + (tt & 1)*8192);
        #pragma unroll
        for (int i = 0; i < 2; i++) {
            int u = tid + i*256;
            int k16 = u >> 8, rt = (u >> 5) & 7, l = u & 31;
            int g = l >> 2, t = l & 3;
            const float* s0 = cA + (rt*16 + g)*40 + k16*16 + 2*t;
            const float* s1 = s0 + 320;
            uint4 v;
            v.x = f2h2(s0[0], s0[1]); v.y = f2h2(s1[0], s1[1]);
            v.z = f2h2(s0[8], s0[9]); v.w = f2h2(s1[8], s1[9]);
            *(uint4*)(hA + k16*2048 + rt*256 + l*8) = v;
        }
        __syncthreads();                 // fp16 A ready

        const uint4* fA = (const uint4*)hA;
        const uint2* fB = (const uint2*)(smc + cur*28672 + 20480);
        #pragma unroll
        for (int ks = 0; ks < 2; ks++) {
            uint4 a[4]; uint2 b[4];
            #pragma unroll
            for (int tm = 0; tm < 4; tm++) a[tm] = fA[ks*256 + (wrt + tm)*32 + lane];
            #pragma unroll
            for (int tn = 0; tn < 4; tn++) b[tn] = fB[ks*512 + (wnb + tn)*32 + lane];
            #pragma unroll
            for (int tm = 0; tm < 4; tm++)
                #pragma unroll
                for (int tn = 0; tn < 4; tn++)
                    mma_f16(acc[tm][tn], a[tm], b[tn]);
        }
    }

    __syncthreads();
    float* Ts = (float*)smh;   // 128*132*4 = 67584 B <= SMEM1_BYTES
    const int wm = (wid >> 2) * 64, wn = (wid & 3) * 32;
    #pragma unroll
    for (int tm = 0; tm < 4; tm++)
        #pragma unroll
        for (int tn = 0; tn < 4; tn++) {
            int m0 = wm + tm*16 + gg, n0 = wn + tn*8 + 2*tq;
            Ts[(n0    )*132 + m0    ] = acc[tm][tn][0];
            Ts[(n0 + 1)*132 + m0    ] = acc[tm][tn][1];
            Ts[(n0    )*132 + m0 + 8] = acc[tm][tn][2];
            Ts[(n0 + 1)*132 + m0 + 8] = acc[tm][tn][3];
        }
    __syncthreads();

    const int n = bm >> 10, pbase = bm & 1023;
    #pragma unroll
    for (int i = 0; i < 16; i++) {
        int u = tid + i*256;
        int k16rel = u >> 9, rest = u & 511;
        int nbg = rest >> 5, l = rest & 31, g = l >> 2, t = l & 3;
        int hrloc = nbg*8 + g, hrAbs = bn + hrloc;
        const float* ts = Ts + hrloc*132 + k16rel*16 + 2*t;
        uint2 v;
        v.x = f2h2(ts[0], ts[1]);
        v.y = f2h2(ts[8], ts[9]);
        size_t dst = (size_t)(n*8 + (hrAbs >> 6))*65536
                   + (size_t)((pbase >> 4) + k16rel)*1024
                   + ((hrAbs >> 3) & 7)*128 + l*4;
        *(uint2*)(g_wsp + dst) = v;
    }
}

// ---------------- DFT over jt on ws slabs (layout-preserving) ---------------
__global__ void k_dft()
{
    const int nh = blockIdx.x, tid = threadIdx.x;
    const __half* slab = g_wsp + (size_t)nh*65536;
    __half* out = g_wc + (size_t)nh*65536;
    #pragma unroll
    for (int it = 0; it < 8; it++) {
        int o4 = tid + it*256;
        float w[8][4];
        #pragma unroll
        for (int jt = 0; jt < 8; jt++) {
            uint2 r = *(const uint2*)(slab + jt*8192 + o4*4);
            __half2 h0 = *(__half2*)&r.x, h1 = *(__half2*)&r.y;
            w[jt][0] = __low2float(h0);  w[jt][1] = __high2float(h0);
            w[jt][2] = __low2float(h1);  w[jt][3] = __high2float(h1);
        }
        #pragma unroll
        for (int c = 0; c < 8; c++) {
            float s[4] = {0,0,0,0};
            #pragma unroll
            for (int jt = 0; jt < 8; jt++) {
                float wgt = DW[c][jt];
                s[0] += wgt*w[jt][0]; s[1] += wgt*w[jt][1];
                s[2] += wgt*w[jt][2]; s[3] += wgt*w[jt][3];
            }
            float sg = (c == 3 || c == 5 || c == 7) ? -1.f : 1.f;
            uint2 v;
            v.x = f2h2(sg*s[0], sg*s[1]);
            v.y = f2h2(sg*s[2], sg*s[3]);
            *(uint2*)(out + c*8192 + o4*4) = v;
        }
    }
}

// ---------------- D-hat packed-A panels from alpha --------------------------
__global__ void k_dmat(const float* __restrict__ alpha)
{
    __shared__ float gs[8][1024];
    const int h = blockIdx.x, tg = blockIdx.y, tid = threadIdx.x;
    for (int i = tid; i < 1024; i += 256) {
        float av[8];
        #pragma unroll
        for (int d = 0; d < 8; d++) av[d] = alpha[h*1024 + ((i + 128*d) & 1023)];
        #pragma unroll
        for (int c = 0; c < 8; c++) {
            float s = 0;
            #pragma unroll
            for (int d = 0; d < 8; d++) s += DW[c][d]*av[d];
            gs[c][i] = s;
        }
    }
    __syncthreads();
    #pragma unroll
    for (int tl = 0; tl < 4; tl++) {
        int t = tg*4 + tl;
        const float* v = gs[VID[t]];
        float s = SGN[t];
        int cb = (t & 1) * 64;
        #pragma unroll
        for (int it = 0; it < 4; it++) {
            int pos = tid + it*256;
            int k16r = pos >> 8, rt = (pos >> 5) & 7, l = pos & 31;
            int g = l >> 2, tq = l & 3;
            int i0 = rt*16 + g, j0 = cb + k16r*16 + 2*tq;
            uint4 o;
            o.x = f2h2(s*v[(j0 - i0) & 1023],     s*v[(j0 + 1 - i0) & 1023]);
            o.y = f2h2(s*v[(j0 - i0 - 8) & 1023], s*v[(j0 - i0 - 7) & 1023]);
            o.z = f2h2(s*v[(j0 + 8 - i0) & 1023], s*v[(j0 + 9 - i0) & 1023]);
            o.w = o.x;
            *(uint4*)(g_dp + (size_t)h*229376 + t*8192 + k16r*2048 + rt*256 + l*8) = o;
        }
    }
}

// ---------------- GEMM2: 8 products per (h, n-pair) -------------------------
__global__ __launch_bounds__(256, 2) void k_gemm2()
{
    extern __shared__ __half smh[];
    const int bp = blockIdx.x, h = blockIdx.y;
    const __half* Ap = g_dp + (size_t)h*229376;
    const __half* B0 = g_wc + (size_t)(bp*16 + h)*65536;
    const __half* B1 = g_wc + (size_t)(bp*16 + 8 + h)*65536;
    __half* Pb = g_Ph + (size_t)(bp*8 + h)*8*16384;

    const int tid = threadIdx.x, wid = tid >> 5, lane = tid & 31;
    const int wrt = (wid >> 2) * 4, wnb = (wid & 3) * 4;
    const int wm = (wid >> 2) * 64, wn = (wid & 3) * 32;
    const int gg = lane >> 2, tq = lane & 3;
    float acc[4][4][4] = {};

    auto load_tile = [&](int tt, int buf){
        __half* dA = smh + buf*16384;
        __half* dB = dA + 8192;
        const __half* As = Ap + (size_t)tt*8192;
        #pragma unroll
        for (int i = 0; i < 4; i++) {
            int c = tid + i*256;
            uint32_t dst = smem_u32(dA + c*8);
            asm volatile("cp.async.cg.shared.global [%0], [%1], 16;"
                         :: "r"(dst), "l"(As + c*8));
        }
        int kb = BK16[tt];
        #pragma unroll
        for (int i = 0; i < 4; i++) {
            int c = tid + i*256;
            int k16s = c >> 8, r = c & 255, nb = r >> 4, lp = r & 15;
            const __half* src = ((nb & 8) ? B1 : B0)
                              + (size_t)(kb + k16s)*1024 + (nb & 7)*128 + lp*8;
            uint32_t dst = smem_u32(dB + k16s*2048 + nb*128 + lp*8);
            asm volatile("cp.async.cg.shared.global [%0], [%1], 16;"
                         :: "r"(dst), "l"(src));
        }
        asm volatile("cp.async.commit_group;" ::: "memory");
    };

    load_tile(0, 0);
    load_tile(1, 1);

    for (int tt = 0; tt < 28; tt++) {
        const int cur = tt % 3;
        if (tt + 1 < 28) asm volatile("cp.async.wait_group 1;" ::: "memory");
        else             asm volatile("cp.async.wait_group 0;" ::: "memory");
        __syncthreads();
        if (tt + 2 < 28) load_tile(tt + 2, (tt + 2) % 3);

        const uint4* fA = (const uint4*)(smh + cur*16384);
        const uint2* fB = (const uint2*)(smh + cur*16384 + 8192);
        #pragma unroll
        for (int ks = 0; ks < 4; ks++) {
            uint4 a[4]; uint2 b[4];
            #pragma unroll
            for (int tm = 0; tm < 4; tm++) a[tm] = fA[ks*256 + (wrt + tm)*32 + lane];
            #pragma unroll
            for (int tn = 0; tn < 4; tn++) b[tn] = fB[ks*512 + (wnb + tn)*32 + lane];
            #pragma unroll
            for (int tm = 0; tm < 4; tm++)
                #pragma unroll
                for (int tn = 0; tn < 4; tn++)
                    mma_f16(acc[tm][tn], a[tm], b[tn]);
        }

        int dc = DEND[tt];
        if (dc >= 0) {
            __half* d = Pb + (size_t)dc*16384;
            #pragma unroll
            for (int tm = 0; tm < 4; tm++)
                #pragma unroll
                for (int tn = 0; tn < 4; tn++) {
                    int m0 = wm + tm*16 + gg, c0 = wn + tn*8 + 2*tq;
                    *(uint32_t*)(d + (m0    )*128 + c0) = f2h2(acc[tm][tn][0], acc[tm][tn][1]);
                    *(uint32_t*)(d + (m0 + 8)*128 + c0) = f2h2(acc[tm][tn][2], acc[tm][tn][3]);
                    acc[tm][tn][0] = acc[tm][tn][1] = acc[tm][tn][2] = acc[tm][tn][3] = 0.f;
                }
        }
    }
}

// ---------------- Combine: y_pt = sum_c MC[pt][c] P_c -> packed-A y ---------
__global__ void k_cmb()
{
    const int bp = blockIdx.x, h = blockIdx.y, tid = threadIdx.x;
    const __half* Pb = g_Ph + (size_t)(bp*8 + h)*8*16384;
    #pragma unroll
    for (int it = 0; it < 8; it++) {
        int task = tid + it*256;
        int nhalf = task >> 10, rest = task & 1023;
        int k16n = rest >> 8, rt = (rest >> 5) & 7, l = rest & 31;
        int g = l >> 2, tq = l & 3;
        int i0 = rt*16 + g;
        int col = nhalf*64 + k16n*16 + 2*tq;

        float y[8][8];
        #pragma unroll
        for (int pt = 0; pt < 8; pt++)
            #pragma unroll
            for (int q = 0; q < 8; q++) y[pt][q] = 0.f;

        #pragma unroll
        for (int c = 0; c < 8; c++) {
            const __half* base = Pb + (size_t)c*16384;
            __half2 a0 = *(const __half2*)(base + (i0    )*128 + col);
            __half2 a1 = *(const __half2*)(base + (i0 + 8)*128 + col);
            __half2 a2 = *(const __half2*)(base + (i0    )*128 + col + 8);
            __half2 a3 = *(const __half2*)(base + (i0 + 8)*128 + col + 8);
            float f0x = __low2float(a0), f0y = __high2float(a0);
            float f1x = __low2float(a1), f1y = __high2float(a1);
            float f2x = __low2float(a2), f2y = __high2float(a2);
            float f3x = __low2float(a3), f3y = __high2float(a3);
            #pragma unroll
            for (int pt = 0; pt < 8; pt++) {
                float m = MC[pt][c];
                y[pt][0] += m*f0x; y[pt][1] += m*f0y;
                y[pt][2] += m*f1x; y[pt][3] += m*f1y;
                y[pt][4] += m*f2x; y[pt][5] += m*f2y;
                y[pt][6] += m*f3x; y[pt][7] += m*f3y;
            }
        }
        #pragma unroll
        for (int pt = 0; pt < 8; pt++) {
            uint4 v;
            v.x = f2h2(y[pt][0], y[pt][1]);
            v.y = f2h2(y[pt][2], y[pt][3]);
            v.z = f2h2(y[pt][4], y[pt][5]);
            v.w = f2h2(y[pt][6], y[pt][7]);
            int panel = (bp*2 + nhalf)*8 + pt;
            *(uint4*)(g_yp + (size_t)panel*65536 + (h*4 + k16n)*2048 + rt*256 + l*8) = v;
        }
    }
}

// ---------------- Stage 3: out = log_cosh(y @ W + b) ------------------------
__global__ __launch_bounds__(256, 2) void k_stage3(const float* __restrict__ bias,
                                                   float* __restrict__ out)
{
    extern __shared__ __half smh[];
    const int bn = blockIdx.x * 128, bm = blockIdx.y * 128;
    float acc[4][4][4] = {};
    const __half* b0 = g_wp + (bn >> 3) * 128;
    gemm_loop(g_yp + (size_t)(bm >> 7)*65536, b0, b0 + 1024, 8192, 8, smh, acc);

    const int tid = threadIdx.x, wid = tid >> 5, lane = tid & 31;
    const int wm = (wid >> 2) * 64, wn = (wid & 3) * 32;
    const int gg = lane >> 2, tq = lane & 3;
    #pragma unroll
    for (int tn = 0; tn < 4; tn++) {
        int n0 = wn + tn*8 + 2*tq;
        float bb0 = bias[bn + n0], bb1 = bias[bn + n0 + 1];
        #pragma unroll
        for (int tm = 0; tm < 4; tm++) {
            int m0 = bm + wm + tm*16 + gg;
            float2 v0 = make_float2(log_cosh_f(acc[tm][tn][0] + bb0),
                                    log_cosh_f(acc[tm][tn][1] + bb1));
            float2 v1 = make_float2(log_cosh_f(acc[tm][tn][2] + bb0),
                                    log_cosh_f(acc[tm][tn][3] + bb1));
            *(float2*)(out + (size_t)(m0    )*EE_ + bn + n0) = v0;
            *(float2*)(out + (size_t)(m0 + 8)*EE_ + bn + n0) = v1;
        }
    }
}

// ---------------- pack kernels ----------------------------------------------
__global__ void k_pack_v(const float* __restrict__ V)   // grid (32 k16, 8)
{
    int k16 = blockIdx.x, nb = blockIdx.y*8 + (threadIdx.x >> 5), l = threadIdx.x & 31;
    int g = l >> 2, t = l & 3;
    const float* r = V + (size_t)(nb*8 + g)*512 + k16*16 + 2*t;
    uint2 v;
    v.x = f2h2(r[0], r[1]); v.y = f2h2(r[8], r[9]);
    *(uint2*)(g_vp + k16*8192 + nb*128 + l*4) = v;
}

__global__ void k_pack_w(const float* __restrict__ W)   // grid (32 k16, 8)
{
    int k16 = blockIdx.x, nb = blockIdx.y*8 + (threadIdx.x >> 5), l = threadIdx.x & 31;
    int g = l >> 2, t = l & 3;
    int e = nb*8 + g, k = k16*16 + 2*t;
    uint2 v;
    v.x = f2h2(W[(size_t)(k    )*512 + e], W[(size_t)(k + 1)*512 + e]);
    v.y = f2h2(W[(size_t)(k + 8)*512 + e], W[(size_t)(k + 9)*512 + e]);
    *(uint2*)(g_wp + k16*8192 + nb*128 + l*4) = v;
}

// ---------------------------------------------------------------------------
extern "C" void kernel_launch(void* const* d_in, const int* in_sizes, int n_in,
                              void* d_out, int out_size)
{
    const float* x     = (const float*)d_in[0];
    const float* alpha = (const float*)d_in[1];
    const float* V     = (const float*)d_in[2];
    const float* W     = (const float*)d_in[3];
    const float* b     = (const float*)d_in[4];
    float* out = (float*)d_out;

    cudaFuncSetAttribute(k_stage1, cudaFuncAttributeMaxDynamicSharedMemorySize, SMEM1_BYTES);
    cudaFuncSetAttribute(k_gemm2, cudaFuncAttributeMaxDynamicSharedMemorySize, SMEM_BYTES);
    cudaFuncSetAttribute(k_stage3, cudaFuncAttributeMaxDynamicSharedMemorySize, SMEM_BYTES);

    k_pack_v<<<dim3(32, 8), 256>>>(V);
    k_pack_w<<<dim3(32, 8), 256>>>(W);
    k_dmat  <<<dim3(8, 7), 256>>>(alpha);

    k_stage1<<<dim3(4, 512), 256, SMEM1_BYTES>>>(x);
    k_dft   <<<512, 256>>>();
    k_gemm2 <<<dim3(32, 8), 256, SMEM_BYTES>>>();
    k_cmb   <<<dim3(32, 8), 256>>>();
    k_stage3<<<dim3(4, 512), 256, SMEM_BYTES>>>(b, out);
}